// round 17
// baseline (speedup 1.0000x reference)
#include <cuda_runtime.h>

#define N_ATOMS 6144
#define ROW4    (N_ATOMS / 4)      // 1536 float4 per row
#define THREADS 256
#define ROWS_PER_BLOCK 4
#define GRID    (N_ATOMS / (2 * ROWS_PER_BLOCK) * 2 / ROWS_PER_BLOCK * ROWS_PER_BLOCK) // see launch
#define NBLOCKS (N_ATOMS / 2 / (ROWS_PER_BLOCK / 2))   // 1536 blocks (2 paired rows per r-step)
#define POISON  2.0e30f

// out[i*N + j] = dist(i,j) if i>j && both non-dummy && sq>0 && dist<=cutoff else 0.
//
// Balance: block b owns rows { b + r*1536, 6143 - (b + r*1536) } for r in {0,1}
// (4 rows total), each swept across the full 6144 columns. Every block is exactly
// half compute / half zero-fill -> uniform block cost -> no tail imbalance.
//
// Mask exactness: dist<=cutoff is evaluated as sq<=TH where TH is the largest
// float whose correctly-rounded sqrt is <= cutoff (ulp walk below). The stored
// value uses 1-instr sqrt.approx (MUFU) -- rel err ~2^-21, mask unaffected.
//
// Dummy atoms: coords poisoned to 2e30 at load. dummy-vs-real -> sq=inf (masked
// by sq<=TH); dummy-vs-dummy -> identical coords -> sq=0 (masked by sq>0).

__device__ __forceinline__ float fsqrt_approx(float x) {
    float y; asm("sqrt.approx.f32 %0, %1;" : "=f"(y) : "f"(x)); return y;
}

__global__ __launch_bounds__(THREADS, 6)
void cell_list_kernel(const int*   __restrict__ species,
                      const float* __restrict__ coords,
                      const int*   __restrict__ cutoff_raw,
                      float*       __restrict__ out)
{
    const int tid = threadIdx.x;
    const int bid = blockIdx.x;
    float4* out4 = reinterpret_cast<float4*>(out);

    // ---- cutoff decode (int scalar or float bits) ----
    const int cbits = *cutoff_raw;
    const float cut = (cbits > 0 && cbits < 1000000) ? (float)cbits
                                                     : __int_as_float(cbits);

    // ---- TH = max float x with sqrt_rn(x) <= cut (exact mask threshold) ----
    float th = cut * cut;
    #pragma unroll
    for (int t = 0; t < 4; t++)                       // walk down if cut*cut overshot
        if (__fsqrt_rn(th) > cut)
            th = __int_as_float(__float_as_int(th) - 1);
    #pragma unroll
    for (int t = 0; t < 4; t++) {                     // walk up to the last included ulp
        float nx = __int_as_float(__float_as_int(th) + 1);
        if (__fsqrt_rn(nx) <= cut) th = nx;
    }

    // ---- paired rows: exactly half of each block's area is below the diagonal ----
    int rows[ROWS_PER_BLOCK];
    #pragma unroll
    for (int r = 0; r < ROWS_PER_BLOCK / 2; r++) {
        rows[2*r]     = bid + r * 1536;               // in [0, 3071]
        rows[2*r + 1] = (N_ATOMS - 1) - rows[2*r];    // in [3072, 6143]
    }

    const float4 z4 = make_float4(0.f, 0.f, 0.f, 0.f);

    #pragma unroll 1
    for (int jp = 0; jp < N_ATOMS / (THREADS * 4); jp++) {   // 6 column passes
        const int j0 = jp * (THREADS * 4) + tid * 4;
        const int col = j0 >> 2;

        // load + poison this thread's 4 j atoms
        float jx[4], jy[4], jz[4];
        #pragma unroll
        for (int u = 0; u < 4; u++) {
            const int j = j0 + u;
            const bool dj = (species[j] == -1);
            jx[u] = dj ? POISON : coords[3*j + 0];
            jy[u] = dj ? POISON : coords[3*j + 1];
            jz[u] = dj ? POISON : coords[3*j + 2];
        }

        #pragma unroll
        for (int r = 0; r < ROWS_PER_BLOCK; r++) {
            const int i = rows[r];
            float4* p = out4 + i * ROW4 + col;

            if (i <= j0) {                      // whole float4 above/on diagonal
                __stcs(p, z4);
                continue;
            }

            const bool di = (species[i] == -1);
            const float cx = di ? POISON : coords[3*i + 0];
            const float cy = di ? POISON : coords[3*i + 1];
            const float cz = di ? POISON : coords[3*i + 2];

            float res[4];
            if (i > j0 + 3) {                   // strictly below diagonal: i>j free
                #pragma unroll
                for (int u = 0; u < 4; u++) {
                    const float dx = cx - jx[u];
                    const float dy = cy - jy[u];
                    const float dz = cz - jz[u];
                    const float sq = dx*dx + dy*dy + dz*dz;
                    const bool m = (sq > 0.f) & (sq <= th);
                    res[u] = m ? fsqrt_approx(sq) : 0.f;
                }
            } else {                            // diagonal-crossing float4
                #pragma unroll
                for (int u = 0; u < 4; u++) {
                    const float dx = cx - jx[u];
                    const float dy = cy - jy[u];
                    const float dz = cz - jz[u];
                    const float sq = dx*dx + dy*dy + dz*dz;
                    const bool m = (i > j0 + u) & (sq > 0.f) & (sq <= th);
                    res[u] = m ? fsqrt_approx(sq) : 0.f;
                }
            }
            __stcs(p, make_float4(res[0], res[1], res[2], res[3]));
        }
    }
}

extern "C" void kernel_launch(void* const* d_in, const int* in_sizes, int n_in,
                              void* d_out, int out_size)
{
    const int*   species = (const int*)  d_in[0];  // [1, 6144] int32
    const float* coords  = (const float*)d_in[1];  // [1, 6144, 3] float32
    const int*   cutoff  = (const int*)  d_in[2];  // scalar (int or float bits)

    // 1536 blocks x 4 rows (2 mirrored pairs) covers all 6144 rows exactly once.
    cell_list_kernel<<<1536, THREADS>>>(species, coords, cutoff, (float*)d_out);
}